// round 5
// baseline (speedup 1.0000x reference)
#include <cuda_runtime.h>

#define NCTA   8
#define NT     288               // 8 row warps + 1 comm warp
#define NRW    8                 // row warps per CTA
#define GWARPS (NCTA * NRW)      // 64 publishing warps
#define RPT    4                 // rows per row-thread: 8*256*4 = 8192
#define NITER  200
#define LROWS  8192

// err = 2^(-2*bits), bits = {2,3,4,5,6,8,10,12}
__constant__ float c_err[8] = {
    6.25e-2f, 1.5625e-2f, 3.90625e-3f, 9.765625e-4f,
    2.44140625e-4f, 1.52587890625e-5f, 9.5367431640625e-7f, 5.9604644775390625e-8f
};

__device__ float g_sum_n;
__device__ float g_inv_sens;

__device__ __forceinline__ float ex2f(float x) {
    float y; asm("ex2.approx.f32 %0, %1;" : "=f"(y) : "f"(x)); return y;
}
__device__ __forceinline__ float lg2f(float x) {
    float y; asm("lg2.approx.f32 %0, %1;" : "=f"(y) : "f"(x)); return y;
}
__device__ __forceinline__ unsigned smem_u32(const void* p) {
    unsigned a;
    asm("{ .reg .u64 t; cvta.to.shared.u64 t, %1; cvt.u32.u64 %0, t; }"
        : "=r"(a) : "l"(p));
    return a;
}
__device__ __forceinline__ unsigned mapa_u32(unsigned laddr, unsigned rank) {
    unsigned r;
    asm("mapa.shared::cluster.u32 %0, %1, %2;" : "=r"(r) : "r"(laddr), "r"(rank));
    return r;
}
__device__ __forceinline__ void st_cluster(unsigned addr, unsigned bits) {
    asm volatile("st.relaxed.cluster.shared::cluster.u32 [%0], %1;"
                 :: "r"(addr), "r"(bits) : "memory");
}
__device__ __forceinline__ unsigned ld_vol_shared(unsigned addr) {
    unsigned v;
    asm volatile("ld.volatile.shared.u32 %0, [%1];" : "=r"(v) : "r"(addr) : "memory");
    return v;
}
__device__ __forceinline__ void st_vol_shared(unsigned addr, unsigned v) {
    asm volatile("st.volatile.shared.u32 [%0], %1;" :: "r"(addr), "r"(v) : "memory");
}

// ---------------------------------------------------------------------------
// Pre-kernel: global input sums (graph-replay deterministic)
// ---------------------------------------------------------------------------
__global__ void da_pre_kernel(const float* __restrict__ n_raw,
                              const float* __restrict__ sens_raw) {
    __shared__ float s1[8], s2[8];
    int t = threadIdx.x;
    float sn = 0.f, ss = 0.f;
    for (int i = t; i < LROWS; i += 256) { sn += n_raw[i]; ss += sens_raw[i]; }
#pragma unroll
    for (int o = 16; o; o >>= 1) {
        sn += __shfl_xor_sync(0xffffffffu, sn, o);
        ss += __shfl_xor_sync(0xffffffffu, ss, o);
    }
    if ((t & 31) == 0) { s1[t >> 5] = sn; s2[t >> 5] = ss; }
    __syncthreads();
    if (t == 0) {
        float a = 0.f, b = 0.f;
#pragma unroll
        for (int w = 0; w < 8; w++) { a += s1[w]; b += s2[w]; }
        g_sum_n    = a * 1e5f + 1e3f * (float)LROWS;
        g_inv_sens = 1.0f / (b + 1e-12f);
    }
}

// ---------------------------------------------------------------------------
// Main kernel: one cluster of 8 CTAs x (8 row warps + 1 comm warp).
// Row warps publish column partials to every CTA over DSMEM; each CTA's comm
// warp is the sole poller, reduces 512->8, computes d_j, broadcasts via smem.
// ---------------------------------------------------------------------------
__global__ void __launch_bounds__(NT, 1) __cluster_dims__(NCTA, 1, 1)
da_main_kernel(const float* __restrict__ theta,
               const float* __restrict__ phi,
               const float* __restrict__ sens_raw,
               const float* __restrict__ n_raw,
               float* __restrict__ out) {
    __shared__ unsigned sbuf[2][GWARPS * 8];  // [slot][gw*8+col], 2KB/slot
    __shared__ unsigned sdw[2][16];           // [slot][0..7]=d, [8]=tot

    const int tid  = threadIdx.x;
    const int lane = tid & 31;
    const int warp = tid >> 5;
    const unsigned FULL = 0xffffffffu;
    const float L2E = 1.4426950408889634f;

    unsigned rank;
    asm("mov.u32 %0, %%cluster_ctarank;" : "=r"(rank));

    const unsigned sbase = smem_u32(&sbuf[0][0]);
    const unsigned dbase = smem_u32(&sdw[0][0]);

    // ---- init rings to phase-sign 1 (iters 0/1 expect sign 0)
    for (int i = tid; i < 2 * GWARPS * 8; i += NT) ((unsigned*)sbuf)[i] = 0x80000000u;
    if (tid < 32) ((unsigned*)sdw)[tid] = 0x80000000u;
    asm volatile("barrier.cluster.arrive.aligned;" ::: "memory");
    asm volatile("barrier.cluster.wait.aligned;" ::: "memory");

    if (warp == NRW) {
        // =================== COMM WARP ===================
        const int mycol = lane & 7;
        float lb_c;
        {
            float q[8];
#pragma unroll
            for (int j = 0; j < 8; j++) q[j] = phi[j] * L2E;
            float m = fmaxf(fmaxf(fmaxf(q[0], q[1]), fmaxf(q[2], q[3])),
                            fmaxf(fmaxf(q[4], q[5]), fmaxf(q[6], q[7])));
            float s = 0.f;
#pragma unroll
            for (int j = 0; j < 8; j++) s += ex2f(q[j] - m);
            lb_c = q[mycol] - m - lg2f(s);
        }

        for (int it = 0; it < NITER; ++it) {
            const int      slot = it & 1;
            const unsigned esgn = (unsigned)((it >> 1) & 1);

            // poll 512 published partials: lane reads idx = lane + 32k
            float v[16];
            unsigned got = 0;
            unsigned pbase = sbase + (unsigned)slot * 2048u + 4u * (unsigned)lane;
            while (got != 0xffffu) {
#pragma unroll
                for (int k = 0; k < 16; k++) {
                    if (!((got >> k) & 1u)) {
                        unsigned b = ld_vol_shared(pbase + 128u * (unsigned)k);
                        if ((b >> 31) == esgn) {
                            v[k] = __uint_as_float(b & 0x7fffffffu);
                            got |= 1u << k;
                        }
                    }
                }
            }
            float T = (((v[0] + v[1]) + (v[2] + v[3])) + ((v[4] + v[5]) + (v[6] + v[7])))
                    + (((v[8] + v[9]) + (v[10] + v[11])) + ((v[12] + v[13]) + (v[14] + v[15])));
            T += __shfl_xor_sync(FULL, T, 8);
            T += __shfl_xor_sync(FULL, T, 16);

            float dc = ex2f(lb_c - lg2f(fmaxf(T, 1e-37f)));
            if (lane < 8)
                st_vol_shared(dbase + (unsigned)slot * 64u + 4u * (unsigned)lane,
                              (__float_as_uint(dc) & 0x7fffffffu) | (esgn << 31));

            // running tot = sum_j T_j * d_j (consumed by row warps on last iter)
            float tg = T * dc;
            tg += __shfl_xor_sync(FULL, tg, 1);
            tg += __shfl_xor_sync(FULL, tg, 2);
            tg += __shfl_xor_sync(FULL, tg, 4);
            if (lane == 0)
                st_vol_shared(dbase + (unsigned)slot * 64u + 32u,
                              (__float_as_uint(tg) & 0x7fffffffu) | (esgn << 31));
        }
        // keep SMEM alive until all peers finish
        asm volatile("barrier.cluster.arrive.aligned;" ::: "memory");
        asm volatile("barrier.cluster.wait.aligned;" ::: "memory");
        return;
    }

    // =================== ROW WARPS ===================
    const int gw   = (int)rank * NRW + warp;          // 0..63
    const int base = ((int)rank * 256 + tid) * RPT;   // first row of this thread

    unsigned remS[NCTA];
    {
        unsigned laddr = sbase + 4u * (unsigned)(gw * 8 + (lane & 7));
#pragma unroll
        for (int t = 0; t < NCTA; t++)
            remS[t] = mapa_u32(laddr, (unsigned)((t + gw) & (NCTA - 1)));
    }

    // per-row constants + K (base-2) + initial row softmax (g = 0)
    const float inv_sumn = 1.0f / g_sum_n;
    const float inv_sens = g_inv_sens;
    const float SC = 50.0f * L2E;

    float a[RPT], p[RPT][8];
    {
        float4 nv = *(const float4*)(n_raw + base);
        float4 sv = *(const float4*)(sens_raw + base);
        float nn[RPT] = { nv.x, nv.y, nv.z, nv.w };
        float se[RPT] = { sv.x, sv.y, sv.z, sv.w };
        const float4* t4 = (const float4*)theta;
#pragma unroll
        for (int e = 0; e < RPT; e++) {
            float n  = nn[e] * 1e5f + 1e3f;
            a[e]     = n * inv_sumn;
            float cs = n * se[e] * inv_sens;
            int   r  = base + e;
            float4 ta = t4[r * 2], tb = t4[r * 2 + 1];
            float x[8];
            x[0] = (ta.x - cs * c_err[0]) * SC;
            x[1] = (ta.y - cs * c_err[1]) * SC;
            x[2] = (ta.z - cs * c_err[2]) * SC;
            x[3] = (ta.w - cs * c_err[3]) * SC;
            x[4] = (tb.x - cs * c_err[4]) * SC;
            x[5] = (tb.y - cs * c_err[5]) * SC;
            x[6] = (tb.z - cs * c_err[6]) * SC;
            x[7] = (tb.w - cs * c_err[7]) * SC;
            float m = fmaxf(fmaxf(fmaxf(x[0], x[1]), fmaxf(x[2], x[3])),
                            fmaxf(fmaxf(x[4], x[5]), fmaxf(x[6], x[7])));
            float S = 0.f;
#pragma unroll
            for (int j = 0; j < 8; j++) { p[e][j] = ex2f(x[j] - m); S += p[e][j]; }
            float ar = __fdividef(a[e], S);
#pragma unroll
            for (int j = 0; j < 8; j++) p[e][j] *= ar;   // P(f1,g0); rows sum to a
        }
    }

    float d[9];
    d[8] = 1.f;

    for (int it = 0; it < NITER; ++it) {
        const int      slot = it & 1;
        const unsigned esgn = (unsigned)((it >> 1) & 1);
        const bool     last = (it == NITER - 1);

        // column partials over 4 rows
        float c0[8];
#pragma unroll
        for (int j = 0; j < 8; j++)
            c0[j] = (p[0][j] + p[1][j]) + (p[2][j] + p[3][j]);

        // butterfly transpose-reduce: lane holds warp col sum for col lane&7
        float z;
        {
            float s0 = __shfl_xor_sync(FULL, c0[0], 4);
            float s1 = __shfl_xor_sync(FULL, c0[1], 4);
            float s2 = __shfl_xor_sync(FULL, c0[2], 4);
            float s3 = __shfl_xor_sync(FULL, c0[3], 4);
            float s4 = __shfl_xor_sync(FULL, c0[4], 4);
            float s5 = __shfl_xor_sync(FULL, c0[5], 4);
            float s6 = __shfl_xor_sync(FULL, c0[6], 4);
            float s7 = __shfl_xor_sync(FULL, c0[7], 4);
            bool hi4 = (lane & 4) != 0;
            float u0 = hi4 ? (c0[4] + s4) : (c0[0] + s0);
            float u1 = hi4 ? (c0[5] + s5) : (c0[1] + s1);
            float u2 = hi4 ? (c0[6] + s6) : (c0[2] + s2);
            float u3 = hi4 ? (c0[7] + s7) : (c0[3] + s3);
            float r0 = __shfl_xor_sync(FULL, u0, 2);
            float r1 = __shfl_xor_sync(FULL, u1, 2);
            float r2 = __shfl_xor_sync(FULL, u2, 2);
            float r3 = __shfl_xor_sync(FULL, u3, 2);
            bool hi2 = (lane & 2) != 0;
            float w0 = hi2 ? (u2 + r2) : (u0 + r0);
            float w1 = hi2 ? (u3 + r3) : (u1 + r1);
            float q0 = __shfl_xor_sync(FULL, w0, 1);
            float q1 = __shfl_xor_sync(FULL, w1, 1);
            z = (lane & 1) ? (w1 + q1) : (w0 + q0);
            z += __shfl_xor_sync(FULL, z, 8);
            z += __shfl_xor_sync(FULL, z, 16);
        }

        // publish to all 8 CTAs (lanes 0-7; sign bit = phase)
        if (lane < 8) {
            unsigned bits = ((__float_as_uint(z + 1e-35f)) & 0x7fffffffu) | (esgn << 31);
            unsigned soff = (unsigned)slot * 2048u;
#pragma unroll
            for (int t = 0; t < NCTA; t++) st_cluster(remS[t] + soff, bits);
        }

        // wait for comm warp's d (and tot on last iter): broadcast LDS polls
        {
            unsigned need  = last ? 0x1ffu : 0xffu;
            unsigned got   = 0;
            unsigned pbase = dbase + (unsigned)slot * 64u;
            while (got != need) {
#pragma unroll
                for (int k = 0; k < 9; k++) {
                    if ((need >> k) & ~(got >> k) & 1u) {
                        unsigned b = ld_vol_shared(pbase + 4u * (unsigned)k);
                        if ((b >> 31) == esgn) {
                            d[k] = __uint_as_float(b & 0x7fffffffu);
                            got |= 1u << k;
                        }
                    }
                }
            }
        }

        // multiplicative row update (skip on last iter; final scaling below)
        if (!last) {
#pragma unroll
            for (int e = 0; e < RPT; e++) {
                float q[8];
#pragma unroll
                for (int j = 0; j < 8; j++) q[j] = p[e][j] * d[j];
                float S = ((q[0] + q[1]) + (q[2] + q[3])) + ((q[4] + q[5]) + (q[6] + q[7]));
                float ar = __fdividef(a[e], S);
#pragma unroll
                for (int j = 0; j < 8; j++) p[e][j] = q[j] * ar;
            }
        }
    }

    // final: P = p * d / tot
    float inv = 1.0f / (d[8] + 1e-40f);
    float4* out4 = (float4*)out;
#pragma unroll
    for (int e = 0; e < RPT; e++) {
        int r = base + e;
        float4 o0, o1;
        o0.x = p[e][0] * d[0] * inv;  o0.y = p[e][1] * d[1] * inv;
        o0.z = p[e][2] * d[2] * inv;  o0.w = p[e][3] * d[3] * inv;
        o1.x = p[e][4] * d[4] * inv;  o1.y = p[e][5] * d[5] * inv;
        o1.z = p[e][6] * d[6] * inv;  o1.w = p[e][7] * d[7] * inv;
        out4[r * 2]     = o0;
        out4[r * 2 + 1] = o1;
    }

    asm volatile("barrier.cluster.arrive.aligned;" ::: "memory");
    asm volatile("barrier.cluster.wait.aligned;" ::: "memory");
}

// ---------------------------------------------------------------------------
extern "C" void kernel_launch(void* const* d_in, const int* in_sizes, int n_in,
                              void* d_out, int out_size) {
    const float* theta    = (const float*)d_in[0];
    const float* phi      = (const float*)d_in[1];
    const float* sens_raw = (const float*)d_in[2];
    const float* n_raw    = (const float*)d_in[3];
    float*       out      = (float*)d_out;

    da_pre_kernel<<<1, 256>>>(n_raw, sens_raw);
    da_main_kernel<<<NCTA, NT>>>(theta, phi, sens_raw, n_raw, out);
}

// round 6
// speedup vs baseline: 1.6968x; 1.6968x over previous
#include <cuda_runtime.h>

#define NCTA   8
#define NT     256
#define NWARP  8
#define RPT    4                 // rows per thread: 8*256*4 = 8192
#define NITER  200
#define LROWS  8192

// err = 2^(-2*bits), bits = {2,3,4,5,6,8,10,12}
__constant__ float c_err[8] = {
    6.25e-2f, 1.5625e-2f, 3.90625e-3f, 9.765625e-4f,
    2.44140625e-4f, 1.52587890625e-5f, 9.5367431640625e-7f, 5.9604644775390625e-8f
};

__device__ float g_sum_n;
__device__ float g_inv_sens;

__device__ __forceinline__ float ex2f(float x) {
    float y; asm("ex2.approx.f32 %0, %1;" : "=f"(y) : "f"(x)); return y;
}
__device__ __forceinline__ float lg2f(float x) {
    float y; asm("lg2.approx.f32 %0, %1;" : "=f"(y) : "f"(x)); return y;
}
__device__ __forceinline__ unsigned smem_u32(const void* p) {
    unsigned a;
    asm("{ .reg .u64 t; cvta.to.shared.u64 t, %1; cvt.u32.u64 %0, t; }"
        : "=r"(a) : "l"(p));
    return a;
}
__device__ __forceinline__ unsigned mapa_u32(unsigned laddr, unsigned rank) {
    unsigned r;
    asm("mapa.shared::cluster.u32 %0, %1, %2;" : "=r"(r) : "r"(laddr), "r"(rank));
    return r;
}
__device__ __forceinline__ void st_cluster_v4(unsigned addr, float4 v) {
    asm volatile("st.relaxed.cluster.shared::cluster.v4.f32 [%0], {%1, %2, %3, %4};"
                 :: "r"(addr), "f"(v.x), "f"(v.y), "f"(v.z), "f"(v.w) : "memory");
}
__device__ __forceinline__ void mbar_arrive_remote(unsigned addr) {
    asm volatile("mbarrier.arrive.release.cluster.shared::cluster.b64 _, [%0];"
                 :: "r"(addr) : "memory");
}
__device__ __forceinline__ void mbar_wait_parity_cluster(unsigned addr, unsigned par) {
    asm volatile(
        "{\n\t"
        ".reg .pred P;\n"
        "W%=:\n\t"
        "mbarrier.try_wait.parity.acquire.cluster.shared::cta.b64 P, [%0], %1, 0x989680;\n\t"
        "@P bra D%=;\n\t"
        "bra W%=;\n"
        "D%=:\n\t"
        "}"
        :: "r"(addr), "r"(par) : "memory");
}

// ---------------------------------------------------------------------------
// Pre-kernel: global input sums (graph-replay deterministic)
// ---------------------------------------------------------------------------
__global__ void da_pre_kernel(const float* __restrict__ n_raw,
                              const float* __restrict__ sens_raw) {
    __shared__ float s1[8], s2[8];
    int t = threadIdx.x;
    float sn = 0.f, ss = 0.f;
    for (int i = t; i < LROWS; i += 256) { sn += n_raw[i]; ss += sens_raw[i]; }
#pragma unroll
    for (int o = 16; o; o >>= 1) {
        sn += __shfl_xor_sync(0xffffffffu, sn, o);
        ss += __shfl_xor_sync(0xffffffffu, ss, o);
    }
    if ((t & 31) == 0) { s1[t >> 5] = sn; s2[t >> 5] = ss; }
    __syncthreads();
    if (t == 0) {
        float a = 0.f, b = 0.f;
#pragma unroll
        for (int w = 0; w < 8; w++) { a += s1[w]; b += s2[w]; }
        g_sum_n    = a * 1e5f + 1e3f * (float)LROWS;
        g_inv_sens = 1.0f / (b + 1e-12f);
    }
}

// ---------------------------------------------------------------------------
// Main kernel: one cluster of 8 CTAs x 256 threads, 4 rows/thread.
// Per-CTA aggregated all-to-all over DSMEM, completion via cluster mbarrier
// (8 arrivals/phase, release/acquire), no software polling anywhere.
// ---------------------------------------------------------------------------
__global__ void __launch_bounds__(NT, 1) __cluster_dims__(NCTA, 1, 1)
da_main_kernel(const float* __restrict__ theta,
               const float* __restrict__ phi,
               const float* __restrict__ sens_raw,
               const float* __restrict__ n_raw,
               float* __restrict__ out) {
    __shared__ __align__(16) float recv[2][64];   // [slot][src*8 + col]
    __shared__ __align__(16) float scol[8];       // CTA column partials
    __shared__ float sred[NWARP][8];              // per-warp column partials
    __shared__ __align__(8) unsigned long long mbar;

    const int tid  = threadIdx.x;
    const int lane = tid & 31;
    const int warp = tid >> 5;
    const unsigned FULL = 0xffffffffu;
    const float L2E = 1.4426950408889634f;

    unsigned rank;
    asm("mov.u32 %0, %%cluster_ctarank;" : "=r"(rank));

    const unsigned recv_base = smem_u32(&recv[0][0]);
    const unsigned mbar_addr = smem_u32(&mbar);

    if (tid == 0)
        asm volatile("mbarrier.init.shared.b64 [%0], %1;"
                     :: "r"(mbar_addr), "r"((unsigned)NCTA) : "memory");
    asm volatile("barrier.cluster.arrive.aligned;" ::: "memory");
    asm volatile("barrier.cluster.wait.aligned;" ::: "memory");

    // publish addresses: warp0 lane t -> target CTA (t+rank)&7
    unsigned rem_data = 0, rem_mb = 0;
    if (warp == 0 && lane < 8) {
        unsigned tgt = ((unsigned)lane + rank) & (NCTA - 1);
        rem_data = mapa_u32(recv_base + rank * 32u, tgt);  // my 8-float strip
        rem_mb   = mapa_u32(mbar_addr, tgt);
    }

    // log_b (base 2) for column class c = lane&7 (all threads)
    const int mycol = lane & 7;
    float lb_c;
    {
        float q[8];
#pragma unroll
        for (int j = 0; j < 8; j++) q[j] = phi[j] * L2E;
        float m = fmaxf(fmaxf(fmaxf(q[0], q[1]), fmaxf(q[2], q[3])),
                        fmaxf(fmaxf(q[4], q[5]), fmaxf(q[6], q[7])));
        float s = 0.f;
#pragma unroll
        for (int j = 0; j < 8; j++) s += ex2f(q[j] - m);
        lb_c = q[mycol] - m - lg2f(s);
    }

    // per-row constants + K (base-2) + initial row softmax (g = 0)
    const int   base = ((int)rank * NT + tid) * RPT;
    const float inv_sumn = 1.0f / g_sum_n;
    const float inv_sens = g_inv_sens;
    const float SC = 50.0f * L2E;

    float a[RPT], p[RPT][8];
    {
        float4 nv = *(const float4*)(n_raw + base);
        float4 sv = *(const float4*)(sens_raw + base);
        float nn[RPT] = { nv.x, nv.y, nv.z, nv.w };
        float se[RPT] = { sv.x, sv.y, sv.z, sv.w };
        const float4* t4 = (const float4*)theta;
#pragma unroll
        for (int e = 0; e < RPT; e++) {
            float n  = nn[e] * 1e5f + 1e3f;
            a[e]     = n * inv_sumn;
            float cs = n * se[e] * inv_sens;
            int   r  = base + e;
            float4 ta = t4[r * 2], tb = t4[r * 2 + 1];
            float x[8];
            x[0] = (ta.x - cs * c_err[0]) * SC;
            x[1] = (ta.y - cs * c_err[1]) * SC;
            x[2] = (ta.z - cs * c_err[2]) * SC;
            x[3] = (ta.w - cs * c_err[3]) * SC;
            x[4] = (tb.x - cs * c_err[4]) * SC;
            x[5] = (tb.y - cs * c_err[5]) * SC;
            x[6] = (tb.z - cs * c_err[6]) * SC;
            x[7] = (tb.w - cs * c_err[7]) * SC;
            float m = fmaxf(fmaxf(fmaxf(x[0], x[1]), fmaxf(x[2], x[3])),
                            fmaxf(fmaxf(x[4], x[5]), fmaxf(x[6], x[7])));
            float S = 0.f;
#pragma unroll
            for (int j = 0; j < 8; j++) { p[e][j] = ex2f(x[j] - m); S += p[e][j]; }
            float ar = __fdividef(a[e], S);
#pragma unroll
            for (int j = 0; j < 8; j++) p[e][j] *= ar;   // P(f1,g0); rows sum to a
        }
    }

    float d[8], Tc = 1.f, dc = 1.f;

    for (int it = 0; it < NITER; ++it) {
        const int slot = it & 1;

        // ---- column partials over this thread's 4 rows
        float c0[8];
#pragma unroll
        for (int j = 0; j < 8; j++)
            c0[j] = (p[0][j] + p[1][j]) + (p[2][j] + p[3][j]);

        // ---- butterfly transpose-reduce: lane holds warp col sum for col lane&7
        float z;
        {
            float s0 = __shfl_xor_sync(FULL, c0[0], 4);
            float s1 = __shfl_xor_sync(FULL, c0[1], 4);
            float s2 = __shfl_xor_sync(FULL, c0[2], 4);
            float s3 = __shfl_xor_sync(FULL, c0[3], 4);
            float s4 = __shfl_xor_sync(FULL, c0[4], 4);
            float s5 = __shfl_xor_sync(FULL, c0[5], 4);
            float s6 = __shfl_xor_sync(FULL, c0[6], 4);
            float s7 = __shfl_xor_sync(FULL, c0[7], 4);
            bool hi4 = (lane & 4) != 0;
            float u0 = hi4 ? (c0[4] + s4) : (c0[0] + s0);
            float u1 = hi4 ? (c0[5] + s5) : (c0[1] + s1);
            float u2 = hi4 ? (c0[6] + s6) : (c0[2] + s2);
            float u3 = hi4 ? (c0[7] + s7) : (c0[3] + s3);
            float r0 = __shfl_xor_sync(FULL, u0, 2);
            float r1 = __shfl_xor_sync(FULL, u1, 2);
            float r2 = __shfl_xor_sync(FULL, u2, 2);
            float r3 = __shfl_xor_sync(FULL, u3, 2);
            bool hi2 = (lane & 2) != 0;
            float w0 = hi2 ? (u2 + r2) : (u0 + r0);
            float w1 = hi2 ? (u3 + r3) : (u1 + r1);
            float q0 = __shfl_xor_sync(FULL, w0, 1);
            float q1 = __shfl_xor_sync(FULL, w1, 1);
            z = (lane & 1) ? (w1 + q1) : (w0 + q0);
            z += __shfl_xor_sync(FULL, z, 8);
            z += __shfl_xor_sync(FULL, z, 16);
        }
        if (lane < 8) sred[warp][lane] = z;
        __syncthreads();   // also gates recv slot reuse (see theory)

        // ---- warp 0: CTA aggregate + publish to all 8 CTAs + arrive
        if (warp == 0) {
            if (lane < 8) {
                float cs = ((sred[0][lane] + sred[1][lane]) + (sred[2][lane] + sred[3][lane]))
                         + ((sred[4][lane] + sred[5][lane]) + (sred[6][lane] + sred[7][lane]));
                scol[lane] = cs;
            }
            __syncwarp();
            if (lane < 8) {
                float4 lo = *(const float4*)&scol[0];
                float4 hi = *(const float4*)&scol[4];
                unsigned ad = rem_data + (unsigned)slot * 256u;
                st_cluster_v4(ad, lo);
                st_cluster_v4(ad + 16u, hi);
                mbar_arrive_remote(rem_mb);   // release orders this lane's stores
            }
        }

        // ---- HW wait: 8 arrivals (one per source CTA), acquire cluster scope
        mbar_wait_parity_cluster(mbar_addr, (unsigned)(it & 1));

        // ---- read 64 words, reduce to column sums (identical order everywhere)
        {
            const float* rv = &recv[slot][0];
            float T = rv[lane] + rv[lane + 32];  // srcs (lane>>3) and (lane>>3)+4
            T += __shfl_xor_sync(FULL, T, 8);
            T += __shfl_xor_sync(FULL, T, 16);
            Tc = T;                              // col sum for col lane&7
        }
        dc = ex2f(lb_c - lg2f(fmaxf(Tc, 1e-37f)));
#pragma unroll
        for (int j = 0; j < 8; j++) d[j] = __shfl_sync(FULL, dc, j, 8);

        // ---- multiplicative row update (skip on last iter)
        if (it != NITER - 1) {
#pragma unroll
            for (int e = 0; e < RPT; e++) {
                float q[8];
#pragma unroll
                for (int j = 0; j < 8; j++) q[j] = p[e][j] * d[j];
                float S = ((q[0] + q[1]) + (q[2] + q[3])) + ((q[4] + q[5]) + (q[6] + q[7]));
                float ar = __fdividef(a[e], S);
#pragma unroll
                for (int j = 0; j < 8; j++) p[e][j] = q[j] * ar;
            }
        }
    }

    // ---- final: P = p * d / tot;  tot = sum_j T_j * d_j
    float tg = Tc * dc;
    tg += __shfl_xor_sync(FULL, tg, 1);
    tg += __shfl_xor_sync(FULL, tg, 2);
    tg += __shfl_xor_sync(FULL, tg, 4);
    float inv = 1.0f / (tg + 1e-40f);

    float4* out4 = (float4*)out;
#pragma unroll
    for (int e = 0; e < RPT; e++) {
        int r = base + e;
        float4 o0, o1;
        o0.x = p[e][0] * d[0] * inv;  o0.y = p[e][1] * d[1] * inv;
        o0.z = p[e][2] * d[2] * inv;  o0.w = p[e][3] * d[3] * inv;
        o1.x = p[e][4] * d[4] * inv;  o1.y = p[e][5] * d[5] * inv;
        o1.z = p[e][6] * d[6] * inv;  o1.w = p[e][7] * d[7] * inv;
        out4[r * 2]     = o0;
        out4[r * 2 + 1] = o1;
    }

    // keep SMEM (mbar/recv) alive until all peers are done
    asm volatile("barrier.cluster.arrive.aligned;" ::: "memory");
    asm volatile("barrier.cluster.wait.aligned;" ::: "memory");
}

// ---------------------------------------------------------------------------
extern "C" void kernel_launch(void* const* d_in, const int* in_sizes, int n_in,
                              void* d_out, int out_size) {
    const float* theta    = (const float*)d_in[0];
    const float* phi      = (const float*)d_in[1];
    const float* sens_raw = (const float*)d_in[2];
    const float* n_raw    = (const float*)d_in[3];
    float*       out      = (float*)d_out;

    da_pre_kernel<<<1, 256>>>(n_raw, sens_raw);
    da_main_kernel<<<NCTA, NT>>>(theta, phi, sens_raw, n_raw, out);
}

// round 7
// speedup vs baseline: 1.8018x; 1.0619x over previous
#include <cuda_runtime.h>

#define NCTA   8
#define NT     256
#define NWARP  8
#define RPT    4                 // rows per thread: 8*256*4 = 8192
#define NITER  200
#define LROWS  8192

// err = 2^(-2*bits), bits = {2,3,4,5,6,8,10,12}
__constant__ float c_err[8] = {
    6.25e-2f, 1.5625e-2f, 3.90625e-3f, 9.765625e-4f,
    2.44140625e-4f, 1.52587890625e-5f, 9.5367431640625e-7f, 5.9604644775390625e-8f
};

__device__ float g_sum_n;
__device__ float g_inv_sens;

__device__ __forceinline__ float ex2f(float x) {
    float y; asm("ex2.approx.f32 %0, %1;" : "=f"(y) : "f"(x)); return y;
}
__device__ __forceinline__ float lg2f(float x) {
    float y; asm("lg2.approx.f32 %0, %1;" : "=f"(y) : "f"(x)); return y;
}
__device__ __forceinline__ unsigned smem_u32(const void* p) {
    unsigned a;
    asm("{ .reg .u64 t; cvta.to.shared.u64 t, %1; cvt.u32.u64 %0, t; }"
        : "=r"(a) : "l"(p));
    return a;
}
__device__ __forceinline__ unsigned mapa_u32(unsigned laddr, unsigned rank) {
    unsigned r;
    asm("mapa.shared::cluster.u32 %0, %1, %2;" : "=r"(r) : "r"(laddr), "r"(rank));
    return r;
}
__device__ __forceinline__ void st_cluster_v4(unsigned addr, float a, float b,
                                              float c, float d) {
    asm volatile("st.relaxed.cluster.shared::cluster.v4.f32 [%0], {%1, %2, %3, %4};"
                 :: "r"(addr), "f"(a), "f"(b), "f"(c), "f"(d) : "memory");
}
__device__ __forceinline__ void mbar_arrive_remote(unsigned addr) {
    asm volatile("mbarrier.arrive.release.cluster.shared::cluster.b64 _, [%0];"
                 :: "r"(addr) : "memory");
}
__device__ __forceinline__ void mbar_wait_parity_cluster(unsigned addr, unsigned par) {
    asm volatile(
        "{\n\t"
        ".reg .pred P;\n"
        "W%=:\n\t"
        "mbarrier.try_wait.parity.acquire.cluster.shared::cta.b64 P, [%0], %1, 0x989680;\n\t"
        "@P bra D%=;\n\t"
        "bra W%=;\n"
        "D%=:\n\t"
        "}"
        :: "r"(addr), "r"(par) : "memory");
}

// ---------------------------------------------------------------------------
// Pre-kernel: global input sums (graph-replay deterministic)
// ---------------------------------------------------------------------------
__global__ void da_pre_kernel(const float* __restrict__ n_raw,
                              const float* __restrict__ sens_raw) {
    __shared__ float s1[8], s2[8];
    int t = threadIdx.x;
    float sn = 0.f, ss = 0.f;
    for (int i = t; i < LROWS; i += 256) { sn += n_raw[i]; ss += sens_raw[i]; }
#pragma unroll
    for (int o = 16; o; o >>= 1) {
        sn += __shfl_xor_sync(0xffffffffu, sn, o);
        ss += __shfl_xor_sync(0xffffffffu, ss, o);
    }
    if ((t & 31) == 0) { s1[t >> 5] = sn; s2[t >> 5] = ss; }
    __syncthreads();
    if (t == 0) {
        float a = 0.f, b = 0.f;
#pragma unroll
        for (int w = 0; w < 8; w++) { a += s1[w]; b += s2[w]; }
        g_sum_n    = a * 1e5f + 1e3f * (float)LROWS;
        g_inv_sens = 1.0f / (b + 1e-12f);
    }
}

// ---------------------------------------------------------------------------
// Main kernel: one cluster of 8 CTAs x 256 threads, 4 rows/thread.
// Per-CTA aggregated all-to-all over DSMEM with cluster mbarrier completion.
// Warp 0 publishes straight from registers (lane t owns target CTA (t+rank)&7).
// ---------------------------------------------------------------------------
__global__ void __launch_bounds__(NT, 1) __cluster_dims__(NCTA, 1, 1)
da_main_kernel(const float* __restrict__ theta,
               const float* __restrict__ phi,
               const float* __restrict__ sens_raw,
               const float* __restrict__ n_raw,
               float* __restrict__ out) {
    __shared__ __align__(16) float recv[2][64];   // [slot][src*8 + col]
    __shared__ __align__(16) float sred[8][NWARP]; // [col][warp] (transposed)
    __shared__ __align__(8) unsigned long long mbar;

    const int tid  = threadIdx.x;
    const int lane = tid & 31;
    const int warp = tid >> 5;
    const unsigned FULL = 0xffffffffu;
    const float L2E = 1.4426950408889634f;

    unsigned rank;
    asm("mov.u32 %0, %%cluster_ctarank;" : "=r"(rank));

    const unsigned recv_base = smem_u32(&recv[0][0]);
    const unsigned mbar_addr = smem_u32(&mbar);

    if (tid == 0)
        asm volatile("mbarrier.init.shared.b64 [%0], %1;"
                     :: "r"(mbar_addr), "r"((unsigned)NCTA) : "memory");
    asm volatile("barrier.cluster.arrive.aligned;" ::: "memory");
    asm volatile("barrier.cluster.wait.aligned;" ::: "memory");

    // publish addresses: warp0 lane t -> target CTA (t+rank)&7 (full 8-float strip)
    unsigned rem_data = 0, rem_mb = 0;
    if (warp == 0 && lane < 8) {
        unsigned tgt = ((unsigned)lane + rank) & (NCTA - 1);
        rem_data = mapa_u32(recv_base + rank * 32u, tgt);
        rem_mb   = mapa_u32(mbar_addr, tgt);
    }

    // log_b (base 2) for column class c = lane&7 (all threads)
    const int mycol = lane & 7;
    float lb_c;
    {
        float q[8];
#pragma unroll
        for (int j = 0; j < 8; j++) q[j] = phi[j] * L2E;
        float m = fmaxf(fmaxf(fmaxf(q[0], q[1]), fmaxf(q[2], q[3])),
                        fmaxf(fmaxf(q[4], q[5]), fmaxf(q[6], q[7])));
        float s = 0.f;
#pragma unroll
        for (int j = 0; j < 8; j++) s += ex2f(q[j] - m);
        lb_c = q[mycol] - m - lg2f(s);
    }

    // per-row constants + K (base-2) + initial row softmax (g = 0)
    const int   base = ((int)rank * NT + tid) * RPT;
    const float inv_sumn = 1.0f / g_sum_n;
    const float inv_sens = g_inv_sens;
    const float SC = 50.0f * L2E;

    float a[RPT], p[RPT][8];
    {
        float4 nv = *(const float4*)(n_raw + base);
        float4 sv = *(const float4*)(sens_raw + base);
        float nn[RPT] = { nv.x, nv.y, nv.z, nv.w };
        float se[RPT] = { sv.x, sv.y, sv.z, sv.w };
        const float4* t4 = (const float4*)theta;
#pragma unroll
        for (int e = 0; e < RPT; e++) {
            float n  = nn[e] * 1e5f + 1e3f;
            a[e]     = n * inv_sumn;
            float cs = n * se[e] * inv_sens;
            int   r  = base + e;
            float4 ta = t4[r * 2], tb = t4[r * 2 + 1];
            float x[8];
            x[0] = (ta.x - cs * c_err[0]) * SC;
            x[1] = (ta.y - cs * c_err[1]) * SC;
            x[2] = (ta.z - cs * c_err[2]) * SC;
            x[3] = (ta.w - cs * c_err[3]) * SC;
            x[4] = (tb.x - cs * c_err[4]) * SC;
            x[5] = (tb.y - cs * c_err[5]) * SC;
            x[6] = (tb.z - cs * c_err[6]) * SC;
            x[7] = (tb.w - cs * c_err[7]) * SC;
            float m = fmaxf(fmaxf(fmaxf(x[0], x[1]), fmaxf(x[2], x[3])),
                            fmaxf(fmaxf(x[4], x[5]), fmaxf(x[6], x[7])));
            float S = 0.f;
#pragma unroll
            for (int j = 0; j < 8; j++) { p[e][j] = ex2f(x[j] - m); S += p[e][j]; }
            float ar = __fdividef(a[e], S);
#pragma unroll
            for (int j = 0; j < 8; j++) p[e][j] *= ar;   // P(f1,g0); rows sum to a
        }
    }

    float d[8], Tc = 1.f, dc = 1.f;
    int ccnt = 0;

    for (int it = 0; it < NITER; ++it) {
        const int slot = it & 1;

        // ---- column partials over this thread's 4 rows
        float c0[8];
#pragma unroll
        for (int j = 0; j < 8; j++)
            c0[j] = (p[0][j] + p[1][j]) + (p[2][j] + p[3][j]);

        // ---- butterfly transpose-reduce: lane holds warp col sum for col lane&7
        float z;
        {
            float s0 = __shfl_xor_sync(FULL, c0[0], 4);
            float s1 = __shfl_xor_sync(FULL, c0[1], 4);
            float s2 = __shfl_xor_sync(FULL, c0[2], 4);
            float s3 = __shfl_xor_sync(FULL, c0[3], 4);
            float s4 = __shfl_xor_sync(FULL, c0[4], 4);
            float s5 = __shfl_xor_sync(FULL, c0[5], 4);
            float s6 = __shfl_xor_sync(FULL, c0[6], 4);
            float s7 = __shfl_xor_sync(FULL, c0[7], 4);
            bool hi4 = (lane & 4) != 0;
            float u0 = hi4 ? (c0[4] + s4) : (c0[0] + s0);
            float u1 = hi4 ? (c0[5] + s5) : (c0[1] + s1);
            float u2 = hi4 ? (c0[6] + s6) : (c0[2] + s2);
            float u3 = hi4 ? (c0[7] + s7) : (c0[3] + s3);
            float r0 = __shfl_xor_sync(FULL, u0, 2);
            float r1 = __shfl_xor_sync(FULL, u1, 2);
            float r2 = __shfl_xor_sync(FULL, u2, 2);
            float r3 = __shfl_xor_sync(FULL, u3, 2);
            bool hi2 = (lane & 2) != 0;
            float w0 = hi2 ? (u2 + r2) : (u0 + r0);
            float w1 = hi2 ? (u3 + r3) : (u1 + r1);
            float q0 = __shfl_xor_sync(FULL, w0, 1);
            float q1 = __shfl_xor_sync(FULL, w1, 1);
            z = (lane & 1) ? (w1 + q1) : (w0 + q0);
            z += __shfl_xor_sync(FULL, z, 8);
            z += __shfl_xor_sync(FULL, z, 16);
        }
        if (lane < 8) sred[lane][warp] = z;        // transposed layout
        __syncthreads();   // also gates recv slot reuse

        // ---- warp 0: CTA aggregate (2 LDS.v4) + register gather + publish
        if (warp == 0) {
            float4 lo = *(const float4*)&sred[mycol][0];
            float4 hi = *(const float4*)&sred[mycol][4];
            float cs = ((lo.x + lo.y) + (lo.z + lo.w)) + ((hi.x + hi.y) + (hi.z + hi.w));
            // gather all 8 column sums into each lane (width-8 shuffles)
            float g0 = __shfl_sync(FULL, cs, 0, 8);
            float g1 = __shfl_sync(FULL, cs, 1, 8);
            float g2 = __shfl_sync(FULL, cs, 2, 8);
            float g3 = __shfl_sync(FULL, cs, 3, 8);
            float g4 = __shfl_sync(FULL, cs, 4, 8);
            float g5 = __shfl_sync(FULL, cs, 5, 8);
            float g6 = __shfl_sync(FULL, cs, 6, 8);
            float g7 = __shfl_sync(FULL, cs, 7, 8);
            if (lane < 8) {
                unsigned ad = rem_data + (unsigned)slot * 256u;
                st_cluster_v4(ad,       g0, g1, g2, g3);
                st_cluster_v4(ad + 16u, g4, g5, g6, g7);
                mbar_arrive_remote(rem_mb);   // release orders this lane's stores
            }
        }

        // ---- HW wait: 8 arrivals (one per source CTA), acquire cluster scope
        mbar_wait_parity_cluster(mbar_addr, (unsigned)(it & 1));

        // ---- read 64 words, reduce to column sums (identical order everywhere)
        {
            const float* rv = &recv[slot][0];
            float T = rv[lane] + rv[lane + 32];  // srcs (lane>>3) and (lane>>3)+4
            T += __shfl_xor_sync(FULL, T, 8);
            T += __shfl_xor_sync(FULL, T, 16);
            Tc = T;                              // col sum for col lane&7
        }
        float dg = lb_c - lg2f(fmaxf(Tc, 1e-37f));
        dc = ex2f(dg);
#pragma unroll
        for (int j = 0; j < 8; j++) d[j] = __shfl_sync(FULL, dc, j, 8);

        // ---- uniform convergence break (bitwise-identical dg in all threads)
        bool near = fabsf(dg) < 1.2e-6f;
        unsigned bal = __ballot_sync(FULL, (lane < 8) ? near : true);
        ccnt = (bal == FULL) ? (ccnt + 1) : 0;
        if (ccnt >= 3) break;                    // final scaling below applies d

        // ---- multiplicative row update (skip on last iter; tail applies d)
        if (it != NITER - 1) {
#pragma unroll
            for (int e = 0; e < RPT; e++) {
                float q[8];
#pragma unroll
                for (int j = 0; j < 8; j++) q[j] = p[e][j] * d[j];
                float S = ((q[0] + q[1]) + (q[2] + q[3])) + ((q[4] + q[5]) + (q[6] + q[7]));
                float ar = __fdividef(a[e], S);
#pragma unroll
                for (int j = 0; j < 8; j++) p[e][j] = q[j] * ar;
            }
        }
    }

    // ---- final: P = p * d / tot;  tot = sum_j T_j * d_j
    float tg = Tc * dc;
    tg += __shfl_xor_sync(FULL, tg, 1);
    tg += __shfl_xor_sync(FULL, tg, 2);
    tg += __shfl_xor_sync(FULL, tg, 4);
    float inv = 1.0f / (tg + 1e-40f);

    float4* out4 = (float4*)out;
#pragma unroll
    for (int e = 0; e < RPT; e++) {
        int r = base + e;
        float4 o0, o1;
        o0.x = p[e][0] * d[0] * inv;  o0.y = p[e][1] * d[1] * inv;
        o0.z = p[e][2] * d[2] * inv;  o0.w = p[e][3] * d[3] * inv;
        o1.x = p[e][4] * d[4] * inv;  o1.y = p[e][5] * d[5] * inv;
        o1.z = p[e][6] * d[6] * inv;  o1.w = p[e][7] * d[7] * inv;
        out4[r * 2]     = o0;
        out4[r * 2 + 1] = o1;
    }

    // keep SMEM (mbar/recv) alive until all peers are done
    asm volatile("barrier.cluster.arrive.aligned;" ::: "memory");
    asm volatile("barrier.cluster.wait.aligned;" ::: "memory");
}

// ---------------------------------------------------------------------------
extern "C" void kernel_launch(void* const* d_in, const int* in_sizes, int n_in,
                              void* d_out, int out_size) {
    const float* theta    = (const float*)d_in[0];
    const float* phi      = (const float*)d_in[1];
    const float* sens_raw = (const float*)d_in[2];
    const float* n_raw    = (const float*)d_in[3];
    float*       out      = (float*)d_out;

    da_pre_kernel<<<1, 256>>>(n_raw, sens_raw);
    da_main_kernel<<<NCTA, NT>>>(theta, phi, sens_raw, n_raw, out);
}